// round 4
// baseline (speedup 1.0000x reference)
#include <cuda_runtime.h>

// Problem constants
#define BSZ   32
#define NSZ   256
#define KSZ   16
#define INC   32
#define OUTC  32
#define XS    (NSZ*INC)   // 8192: per-sample stride in x and out

// Scratch (allocation-free)
__device__ float  g_Tpart[8 * 2 * BSZ * KSZ * OUTC];  // [Bg][p][s][k][o]
__device__ float4 g_wdT4[KSZ * OUTC * INC / 4];       // [k][o][i] as float4

// ---------------------------------------------------------------------------
// Kernel A: block = (k in 16, Bg in 8 groups of 4 B's). 256 threads.
//  Phase 0: load W slice w_off[(o,i), k, Bg*4..+4) -> smem (padded f4 layout)
//           (Bg==0 blocks also transpose w_diag -> g_wdT)
//  Phase 1: gather-pool S[s][Bl][i] = sum_r x[s, perm[(Bg*4+Bl)*8+r], i]
//           (full 128B coalesced row reads, software-pipelined batches)
//  Phase 2: register-tiled contraction over (i, Bl):
//           thread = (sp 16, og 4, Bq 4): acc[2 s][2 par][8 o]
//  Phase 3: staging reduce over Bq -> g_Tpart partials
// ---------------------------------------------------------------------------
__global__ void __launch_bounds__(256) kernelA(
    const float* __restrict__ x,
    const float* __restrict__ w_diag,
    const float* __restrict__ w_off,
    const int*   __restrict__ perm)
{
    // W4 in [0,1152), S4 in [1152,2304). Reused as float stage[256*33] after compute.
    __shared__ float4 buf4[2304];
    float4* W4 = buf4;
    float4* S4 = buf4 + 1152;
    float*  Wf = (float*)W4;
    float*  Sf = (float*)S4;
    float*  stage = (float*)buf4;

    const int bx = blockIdx.x;
    const int k  = bx >> 3;
    const int Bg = bx & 7;
    const int t  = threadIdx.x;

    // ---- W tile global loads (issued early, consumed after gather) ----
    const float4* woff4 = (const float4*)w_off;  // [c][k][B/4]: c*128 + k*8 + (B>>2)
    float4 wreg[4];
#pragma unroll
    for (int j = 0; j < 4; j++) {
        int c = j * 256 + t;                      // c = o*32 + i
        wreg[j] = __ldg(&woff4[c * 128 + k * 8 + Bg]);
    }

    // ---- w_diag transpose (one block per k) ----
    if (Bg == 0) {
        float* gw = (float*)g_wdT4;
#pragma unroll
        for (int j = 0; j < 4; j++) {
            int e = j * 256 + t;                  // e = o*32 + i
            gw[k * 1024 + e] = __ldg(&w_diag[e * 16 + k]);
        }
    }

    // ---- gather-pool S slice: rows (s, Bl) for Bl in [0,4) ----
    {
        int warp = t >> 5, lane = t & 31;
        int gbase = warp * 16;                    // 16 (s,Bl) groups per warp
#pragma unroll
        for (int half = 0; half < 2; half++) {
            float v[8][8];
#pragma unroll
            for (int q = 0; q < 8; q++) {
                int grp = gbase + half * 8 + q;
                int s = grp >> 2, Bl = grp & 3;
                const float* xs = x + s * XS + lane;
#pragma unroll
                for (int r = 0; r < 8; r++) {
                    int n = __ldg(&perm[Bg * 32 + Bl * 8 + r]);
                    v[q][r] = __ldg(&xs[n * 32]);
                }
            }
#pragma unroll
            for (int q = 0; q < 8; q++) {
                int grp = gbase + half * 8 + q;
                int s = grp >> 2, Bl = grp & 3;
                float a = ((v[q][0] + v[q][1]) + (v[q][2] + v[q][3]))
                        + ((v[q][4] + v[q][5]) + (v[q][6] + v[q][7]));
                Sf[(s * 4 + Bl) * 36 + lane] = a;  // S4[(s*4+Bl)*9 + iq]
            }
        }
    }

    // ---- store W regs to padded smem: W4[(o*4+Bl)*9 + iq] ----
#pragma unroll
    for (int j = 0; j < 4; j++) {
        int c = j * 256 + t;
        int o = c >> 5, i = c & 31;
        Wf[(o * 4 + 0) * 36 + i] = wreg[j].x;
        Wf[(o * 4 + 1) * 36 + i] = wreg[j].y;
        Wf[(o * 4 + 2) * 36 + i] = wreg[j].z;
        Wf[(o * 4 + 3) * 36 + i] = wreg[j].w;
    }
    __syncthreads();

    // ---- main contraction ----
    const int sp = t >> 4;          // 16 s-pairs: s0=sp, s1=sp+16
    const int og = (t >> 2) & 3;    // o = og + 4*oo
    const int Bq = t & 3;

    const float4* Su0 = S4 + (sp * 4 + Bq) * 9;
    const float4* Su1 = S4 + ((sp + 16) * 4 + Bq) * 9;
    const float4* Sv0 = S4 + (sp * 4 + (Bq ^ 1)) * 9;
    const float4* Sv1 = S4 + ((sp + 16) * 4 + (Bq ^ 1)) * 9;

    float acc[2][2][8];
#pragma unroll
    for (int j = 0; j < 32; j++) ((float*)acc)[j] = 0.f;

#pragma unroll
    for (int iq = 0; iq < 8; iq++) {
        float4 u0 = Su0[iq], u1 = Su1[iq], v0 = Sv0[iq], v1 = Sv1[iq];
#pragma unroll
        for (int oo = 0; oo < 8; oo++) {
            int o = og + 4 * oo;
            float4 w = W4[(o * 4 + Bq) * 9 + iq];
            acc[0][0][oo] += w.x*u0.x + w.y*u0.y + w.z*u0.z + w.w*u0.w;
            acc[0][1][oo] += w.x*v0.x + w.y*v0.y + w.z*v0.z + w.w*v0.w;
            acc[1][0][oo] += w.x*u1.x + w.y*u1.y + w.z*u1.z + w.w*u1.w;
            acc[1][1][oo] += w.x*v1.x + w.y*v1.y + w.z*v1.z + w.w*v1.w;
        }
    }

    // ---- reduce over Bq via staging ----
    __syncthreads();   // done reading W4/S4; buf4 becomes stage
#pragma unroll
    for (int ss = 0; ss < 2; ss++)
#pragma unroll
        for (int p = 0; p < 2; p++)
#pragma unroll
            for (int oo = 0; oo < 8; oo++)
                stage[t * 33 + (ss * 16 + p * 8 + oo)] = acc[ss][p][oo];
    __syncthreads();

    {
        int sp2 = t >> 4, og2 = (t >> 2) & 3, jq = t & 3;
#pragma unroll
        for (int jj = 0; jj < 8; jj++) {
            int j = jq * 8 + jj;
            float v = 0.f;
#pragma unroll
            for (int b = 0; b < 4; b++)
                v += stage[(sp2 * 16 + og2 * 4 + b) * 33 + j];
            int ss = j >> 4, p = (j >> 3) & 1, oo = j & 7;
            int s = sp2 + 16 * ss, o = og2 + 4 * oo;
            g_Tpart[(((Bg * 2 + p) * 32 + s) * 16 + k) * 32 + o] = v;
        }
    }
}

// ---------------------------------------------------------------------------
// Kernel B: finalize. block = (s in 32, k-quad in 4). 512 threads.
//   out[s, perm[a], o] = T[p][s][k][o]/256 + sum_i xp[s,a,i]*wdT[k][o][i] + b1[o]
// ---------------------------------------------------------------------------
__global__ void __launch_bounds__(512) kernelB(
    const float* __restrict__ x,
    const float* __restrict__ b1,
    const int*   __restrict__ perm,
    float*       __restrict__ out)
{
    __shared__ float4 wdsh4[32 * 33];   // [o*33 + kk*8 + iq]
    __shared__ float4 xpsh4[64 * 8];    // [(kk*16+a)*8 + iq]
    __shared__ float  tsh[4 * 64];      // [kk][p][o]
    __shared__ float  bsh[32];
    __shared__ int    permS[64];

    int b = blockIdx.x;
    int s = b >> 2, kq = b & 3;
    int t = threadIdx.x;

    if (t < 64) permS[t] = __ldg(&perm[kq * 64 + t]);
    if (t >= 64 && t < 96) bsh[t - 64] = b1[t - 64];
    __syncthreads();

    // wdT slice (4 k's)
#pragma unroll
    for (int j = 0; j < 2; j++) {
        int e = j * 512 + t;                    // e = kk*256 + o*8 + iq
        int kk = e >> 8, rem = e & 255;
        int o = rem >> 3, iq = rem & 7;
        wdsh4[o * 33 + kk * 8 + iq] = g_wdT4[(kq * 4 + kk) * 256 + rem];
    }
    // xp gather (64 rows x 32 floats, coalesced per row)
    {
        float* xpf = (float*)xpsh4;
#pragma unroll
        for (int j = 0; j < 4; j++) {
            int e = j * 512 + t;
            int row = e >> 5, i = e & 31;
            xpf[e] = x[s * XS + permS[row] * 32 + i];
        }
    }
    // T reduction over Bg
    if (t < 256) {
        int kk = t >> 6, p = (t >> 5) & 1, o = t & 31;
        int k = kq * 4 + kk;
        float acc = 0.f;
#pragma unroll
        for (int Bg = 0; Bg < 8; Bg++)
            acc += g_Tpart[(((Bg * 2 + p) * 32 + s) * 16 + k) * 32 + o];
        tsh[kk * 64 + p * 32 + o] = acc * (1.f / 256.f);
    }
    __syncthreads();

    int a = t >> 5, o = t & 31;
    int pa = (a >> 3) & 1;
#pragma unroll
    for (int kk = 0; kk < 4; kk++) {
        float acc = tsh[kk * 64 + pa * 32 + o] + bsh[o];
#pragma unroll
        for (int iq = 0; iq < 8; iq++) {
            float4 xv = xpsh4[(kk * 16 + a) * 8 + iq];   // broadcast
            float4 wv = wdsh4[o * 33 + kk * 8 + iq];     // conflict-free
            acc += wv.x * xv.x + wv.y * xv.y + wv.z * xv.z + wv.w * xv.w;
        }
        int n = permS[kk * 16 + a];
        out[s * XS + n * 32 + o] = acc;
    }
}

// ---------------------------------------------------------------------------
extern "C" void kernel_launch(void* const* d_in, const int* in_sizes, int n_in,
                              void* d_out, int out_size)
{
    const float* x      = (const float*)d_in[0];
    const float* w_diag = (const float*)d_in[1];
    const float* w_off  = (const float*)d_in[2];
    const float* b1     = (const float*)d_in[3];
    const int*   perm   = (const int*)d_in[4];
    float* out = (float*)d_out;

    kernelA<<<128, 256>>>(x, w_diag, w_off, perm);
    kernelB<<<128, 512>>>(x, b1, perm, out);
}